// round 13
// baseline (speedup 1.0000x reference)
#include <cuda_runtime.h>
#include <cuda_bf16.h>
#include <math.h>
#include <stdint.h>

#define N_NODES 50000
#define N_EDGES 640000
#define FEAT    128
#define HIDDEN  512
#define BATCH   32

#define SCAN_B 256
#define SCAN_G ((N_NODES + SCAN_B - 1) / SCAN_B)   // 196

// ---------------- scratch (static device globals; no allocation) ----------------
__device__ float g_h[(size_t)N_NODES * FEAT];
__device__ float g_h2[(size_t)N_NODES * FEAT];
__device__ int   g_eidx[2 * N_EDGES];
__device__ int   g_is64;
__device__ int   g_degi[N_NODES];
__device__ int   g_bsum[SCAN_G];
__device__ int   g_rowstart[N_NODES + 1];
__device__ int   g_cursor[N_NODES];
__device__ int   g_csr[N_EDGES];
__device__ float g_me[BATCH * FEAT];
__device__ float g_stats[64];
// pre-split stacked weights: [layer][hi/lo][k(256) * n(128)] bf16
__device__ __nv_bfloat16 g_wsplit[2][2][256 * 128];

__device__ __forceinline__ uint32_t smem_u32(const void* p) {
    uint32_t a;
    asm("{ .reg .u64 t; cvta.to.shared.u64 t, %1; cvt.u32.u64 %0, t; }" : "=r"(a) : "l"(p));
    return a;
}

// ---------------- detect dtype + zero degrees (merged) ----------------
__global__ void k_detect_zero(const unsigned int* __restrict__ raw) {
    int i = blockIdx.x * blockDim.x + threadIdx.x;
    if (i < N_NODES) g_degi[i] = 0;
    if (blockIdx.x == 0) {
        __shared__ int any_nz;
        if (threadIdx.x == 0) any_nz = 0;
        __syncthreads();
        int nz = 0;
        for (int p = threadIdx.x; p < 2048; p += 256)
            if (raw[2 * p + 1] != 0u) nz = 1;
        if (nz) atomicOr(&any_nz, 1);
        __syncthreads();
        if (threadIdx.x == 0) g_is64 = any_nz ? 0 : 1;
    }
}

__global__ void k_convert_count(const void* __restrict__ raw) {
    int e = blockIdx.x * blockDim.x + threadIdx.x;
    if (e >= 2 * N_EDGES) return;
    long long v;
    if (g_is64) v = ((const long long*)raw)[e];
    else        v = (long long)(((const int*)raw)[e]);
    int iv = (int)v;
    if (iv < 0) iv = 0;
    if (iv >= N_NODES) iv = N_NODES - 1;
    g_eidx[e] = iv;
    if (e >= N_EDGES) atomicAdd(&g_degi[iv], 1);
}

// ---------------- hierarchical scan ----------------
__global__ void k_blocksum() {
    __shared__ int red[SCAN_B];
    int i = blockIdx.x * SCAN_B + threadIdx.x;
    red[threadIdx.x] = (i < N_NODES) ? g_degi[i] : 0;
    __syncthreads();
    for (int off = SCAN_B / 2; off > 0; off >>= 1) {
        if (threadIdx.x < off) red[threadIdx.x] += red[threadIdx.x + off];
        __syncthreads();
    }
    if (threadIdx.x == 0) g_bsum[blockIdx.x] = red[0];
}

__global__ void k_scatter_rows() {
    __shared__ int wsum[8];
    __shared__ int boff;
    int tid = threadIdx.x;
    if (tid == 0) boff = 0;
    __syncthreads();
    if (tid < (int)blockIdx.x) atomicAdd(&boff, g_bsum[tid]);
    int i = blockIdx.x * SCAN_B + tid;
    int lane = tid & 31, wid = tid >> 5;
    int d = (i < N_NODES) ? g_degi[i] : 0;
    int v = d;
    #pragma unroll
    for (int off = 1; off < 32; off <<= 1) {
        int t = __shfl_up_sync(0xffffffffu, v, off);
        if (lane >= off) v += t;
    }
    if (lane == 31) wsum[wid] = v;
    __syncthreads();
    if (wid == 0 && lane < 8) {
        int w = wsum[lane];
        #pragma unroll
        for (int off = 1; off < 8; off <<= 1) {
            int t = __shfl_up_sync(0xffu, w, off);
            if (lane >= off) w += t;
        }
        wsum[lane] = w;
    }
    __syncthreads();
    int excl = v - d + (wid > 0 ? wsum[wid - 1] : 0) + boff;
    if (i < N_NODES) {
        g_rowstart[i] = excl;
        g_cursor[i]   = excl;
    }
    if (i == N_NODES - 1) g_rowstart[N_NODES] = excl + d;
}

__global__ void k_fill() {
    int e = blockIdx.x * blockDim.x + threadIdx.x;
    if (e < N_EDGES) {
        int d = g_eidx[N_EDGES + e];
        int pos = atomicAdd(&g_cursor[d], 1);
        if (pos >= 0 && pos < N_EDGES) g_csr[pos] = g_eidx[e];
    }
}

// ---------------- weight pre-split ----------------
__global__ void k_prep_w(const float* __restrict__ W1r, const float* __restrict__ W1o,
                         const float* __restrict__ W2r, const float* __restrict__ W2o)
{
    int idx = blockIdx.x * blockDim.x + threadIdx.x;
    if (idx >= 2 * 256 * 128) return;
    int l = idx >> 15;
    int e = idx & 32767;
    int k = e >> 7, n = e & 127;
    const float* W = (k < 128) ? (l ? W2r : W1r) : (l ? W2o : W1o);
    float v = W[(size_t)(k & 127) * 128 + n];
    __nv_bfloat16 h = __float2bfloat16(v);
    __nv_bfloat16 lo = __float2bfloat16(v - __bfloat162float(h));
    g_wsplit[l][0][e] = h;
    g_wsplit[l][1][e] = lo;
}

// ---------------- mma.sync helpers ----------------
__device__ __forceinline__ void hmma16816(float* c, const uint32_t* a,
                                          uint32_t b0, uint32_t b1) {
    asm volatile(
        "mma.sync.aligned.m16n8k16.row.col.f32.bf16.bf16.f32 "
        "{%0,%1,%2,%3}, {%4,%5,%6,%7}, {%8,%9}, {%0,%1,%2,%3};"
        : "+f"(c[0]), "+f"(c[1]), "+f"(c[2]), "+f"(c[3])
        : "r"(a[0]), "r"(a[1]), "r"(a[2]), "r"(a[3]), "r"(b0), "r"(b1));
}
__device__ __forceinline__ void ldsm_x4(uint32_t* r, uint32_t addr) {
    asm volatile("ldmatrix.sync.aligned.m8n8.x4.shared.b16 {%0,%1,%2,%3}, [%4];"
                 : "=r"(r[0]), "=r"(r[1]), "=r"(r[2]), "=r"(r[3]) : "r"(addr));
}
__device__ __forceinline__ void ldsm_x4t(uint32_t* r, uint32_t addr) {
    asm volatile("ldmatrix.sync.aligned.m8n8.x4.trans.shared.b16 {%0,%1,%2,%3}, [%4];"
                 : "=r"(r[0]), "=r"(r[1]), "=r"(r[2]), "=r"(r[3]) : "r"(addr));
}
__device__ __forceinline__ void split_bf16(float v, __nv_bfloat16& h, __nv_bfloat16& l) {
    h = __float2bfloat16(v);
    l = __float2bfloat16(v - __bfloat162float(h));
}
__device__ __forceinline__ uint32_t pack2(__nv_bfloat16 a, __nv_bfloat16 b) {
    return (uint32_t)__bfloat16_as_ushort(a) | ((uint32_t)__bfloat16_as_ushort(b) << 16);
}

// ---------------- fused gather + layer GEMM ----------------
// agg = mean_{src} base[src] computed in-CTA into SMEM bf16 planes,
// then h_out = relu([agg | h_in] @ Wstack + b).
#define SP_AG 136    // agg plane pitch in bf16 elems (272 B)
#define SP_A  40     // h-chunk pitch
#define SP_B  136
// dynamic smem layout (bytes)
#define SMO_AGH  0
#define SMO_AGL  34816
#define SMO_A    69632          // 2 planes x 128 x SP_A x 2 = 20480
#define SMO_B    90112          // 2 planes x 32 x SP_B x 2 = 17408
#define SM_TOT   107520

__global__ __launch_bounds__(256, 2) void k_layer_fused(
    const float* __restrict__ Hext,
    const float* __restrict__ bias,
    int layer, int h_sel, int c_sel, int M)
{
    extern __shared__ char smem[];
    const float* Hin = h_sel ? (const float*)g_h : Hext;
    float*       C   = c_sel ? g_h2 : g_h;
    int tid = threadIdx.x;
    int wid = tid >> 5, lane = tid & 31;
    int row0 = blockIdx.x * 128;
    int warp_m = wid >> 1, warp_n = wid & 1;
    int wrow = warp_m * 32;
    int wcol = warp_n * 64;

    uint32_t sbase  = smem_u32(smem);
    uint32_t agh_b  = sbase + SMO_AGH;
    uint32_t agl_b  = sbase + SMO_AGL;
    uint32_t a_b    = sbase + SMO_A;
    uint32_t b_b    = sbase + SMO_B;
    const uint32_t A_IMG = 128 * SP_A * 2;
    const uint32_t B_IMG = 32 * SP_B * 2;

    // ---- gather phase: warp wid handles rows wid*16 .. wid*16+15 ----
    {
        #pragma unroll 1
        for (int t = 0; t < 16; ++t) {
            int r  = wid * 16 + t;
            int gr = row0 + r;
            float4 acc = make_float4(0.f, 0.f, 0.f, 0.f);
            if (gr < M) {
                int beg = g_rowstart[gr];
                int end = g_rowstart[gr + 1];
                for (int j = beg; j < end; ++j) {
                    int s = g_csr[j];
                    float4 v = *(const float4*)&Hin[(size_t)s * 128 + lane * 4];
                    acc.x += v.x; acc.y += v.y; acc.z += v.z; acc.w += v.w;
                }
                float invd = 1.0f / fmaxf((float)(end - beg), 1.0f);
                acc.x *= invd; acc.y *= invd; acc.z *= invd; acc.w *= invd;
            }
            __nv_bfloat16 h0, l0, h1, l1, h2, l2, h3, l3;
            split_bf16(acc.x, h0, l0); split_bf16(acc.y, h1, l1);
            split_bf16(acc.z, h2, l2); split_bf16(acc.w, h3, l3);
            uint32_t doff = (uint32_t)r * (SP_AG * 2) + (uint32_t)lane * 8;
            *(uint2*)(smem + SMO_AGH + doff) = make_uint2(pack2(h0, h1), pack2(h2, h3));
            *(uint2*)(smem + SMO_AGL + doff) = make_uint2(pack2(l0, l1), pack2(l2, l3));
        }
    }
    __syncthreads();

    // ldsm thread-address components
    int a_lr    = lane & 7;
    int a_half  = (lane >> 3) & 1;
    int a_khalf = lane >> 4;
    uint32_t aA_row = (uint32_t)(wrow + a_lr + a_half * 8);
    uint32_t a_off0 = aA_row * (SP_A * 2) + (uint32_t)a_khalf * 16;      // h-chunk planes
    uint32_t g_off0 = aA_row * (SP_AG * 2) + (uint32_t)a_khalf * 16;     // agg planes
    int b_lr   = lane & 15;
    int b_csel = lane >> 4;

    const __nv_bfloat16* Whi = g_wsplit[layer][0];
    const __nv_bfloat16* Wlo = g_wsplit[layer][1];

    float acc[2][8][4];
    #pragma unroll
    for (int mb = 0; mb < 2; ++mb)
        #pragma unroll
        for (int nb = 0; nb < 8; ++nb)
            #pragma unroll
            for (int q = 0; q < 4; ++q) acc[mb][nb][q] = 0.f;

    for (int c = 0; c < 8; ++c) {
        int k0 = c * 32;
        bool use_agg = (c < 4);

        if (!use_agg) {
            int ka = k0 & 127;
            // stage h chunk (float4 + split)
            #pragma unroll
            for (int it = 0; it < 4; ++it) {
                int idx = tid + it * 256;
                int m  = idx >> 3;
                int k4 = (idx & 7) * 4;
                int gr = row0 + m;
                float4 v = make_float4(0.f, 0.f, 0.f, 0.f);
                if (gr < M) v = *(const float4*)&Hin[(size_t)gr * 128 + ka + k4];
                __nv_bfloat16 h0, l0, h1, l1, h2, l2, h3, l3;
                split_bf16(v.x, h0, l0); split_bf16(v.y, h1, l1);
                split_bf16(v.z, h2, l2); split_bf16(v.w, h3, l3);
                uint32_t doff = (uint32_t)m * (SP_A * 2) + (uint32_t)k4 * 2;
                *(uint2*)(smem + SMO_A + doff)         = make_uint2(pack2(h0, h1), pack2(h2, h3));
                *(uint2*)(smem + SMO_A + A_IMG + doff) = make_uint2(pack2(l0, l1), pack2(l2, l3));
            }
        }
        // stage B chunk (pure copy)
        #pragma unroll
        for (int it = 0; it < 4; ++it) {
            int idx = tid + it * 256;
            int kk = idx >> 5;
            int n4 = (idx & 31) * 4;
            uint32_t soff = (uint32_t)(k0 + kk) * 128 + (uint32_t)n4;
            uint32_t doff = (uint32_t)kk * (SP_B * 2) + (uint32_t)n4 * 2;
            *(uint2*)(smem + SMO_B + doff)         = *(const uint2*)&Whi[soff];
            *(uint2*)(smem + SMO_B + B_IMG + doff) = *(const uint2*)&Wlo[soff];
        }
        __syncthreads();

        #pragma unroll
        for (int kk = 0; kk < 2; ++kk) {
            uint32_t ah[2][4], al[2][4];
            #pragma unroll
            for (int mb = 0; mb < 2; ++mb) {
                if (use_agg) {
                    uint32_t ao = g_off0 + (uint32_t)(mb * 16) * (SP_AG * 2)
                                + (uint32_t)(k0 + kk * 16) * 2;
                    ldsm_x4(ah[mb], agh_b + ao);
                    ldsm_x4(al[mb], agl_b + ao);
                } else {
                    uint32_t ao = a_off0 + (uint32_t)(mb * 16) * (SP_A * 2) + (uint32_t)kk * 32;
                    ldsm_x4(ah[mb], a_b + ao);
                    ldsm_x4(al[mb], a_b + A_IMG + ao);
                }
            }
            uint32_t b_row = (uint32_t)(kk * 16 + b_lr) * (SP_B * 2);
            #pragma unroll
            for (int nb2 = 0; nb2 < 4; ++nb2) {
                uint32_t bh[4], bl[4];
                uint32_t bcol = (uint32_t)(wcol + nb2 * 16 + b_csel * 8) * 2;
                ldsm_x4t(bh, b_b + b_row + bcol);
                ldsm_x4t(bl, b_b + B_IMG + b_row + bcol);
                #pragma unroll
                for (int hh = 0; hh < 2; ++hh) {
                    int nb = nb2 * 2 + hh;
                    #pragma unroll
                    for (int mb = 0; mb < 2; ++mb) {
                        hmma16816(acc[mb][nb], ah[mb], bh[2 * hh], bh[2 * hh + 1]);
                        hmma16816(acc[mb][nb], ah[mb], bl[2 * hh], bl[2 * hh + 1]);
                        hmma16816(acc[mb][nb], al[mb], bh[2 * hh], bh[2 * hh + 1]);
                    }
                }
            }
        }
        __syncthreads();
    }

    int g   = lane >> 2;
    int tig = lane & 3;
    #pragma unroll
    for (int nb = 0; nb < 8; ++nb) {
        int col = wcol + nb * 8 + tig * 2;
        float bb0 = bias[col], bb1 = bias[col + 1];
        #pragma unroll
        for (int mb = 0; mb < 2; ++mb) {
            int r0g = row0 + wrow + mb * 16 + g;
            int r1g = r0g + 8;
            float* a = acc[mb][nb];
            if (r0g < M)
                *(float2*)&C[(size_t)r0g * 128 + col] =
                    make_float2(fmaxf(a[0] + bb0, 0.f), fmaxf(a[1] + bb1, 0.f));
            if (r1g < M)
                *(float2*)&C[(size_t)r1g * 128 + col] =
                    make_float2(fmaxf(a[2] + bb0, 0.f), fmaxf(a[3] + bb1, 0.f));
        }
    }
}

// ---------------- projection ----------------
__global__ void k_proj(const float* __restrict__ lh, const float* __restrict__ Wp,
                       const float* __restrict__ bp)
{
    int idx = blockIdx.x * blockDim.x + threadIdx.x;
    if (idx >= BATCH * 128) return;
    int b = idx >> 7, j = idx & 127;
    float acc = bp[j];
    const float* lr = &lh[(size_t)b * HIDDEN];
    #pragma unroll 8
    for (int k = 0; k < HIDDEN; ++k)
        acc += lr[k] * Wp[(size_t)k * 128 + j];
    g_me[b * 128 + j] = acc;
}

// ---------------- scores ----------------
__global__ void k_scores(float* __restrict__ out)
{
    __shared__ float sme[32 * 129];
    int tid = threadIdx.x;
    for (int idx = tid; idx < 32 * 128; idx += blockDim.x) {
        int b = idx >> 7, k = idx & 127;
        sme[b * 129 + k] = g_me[idx];
    }
    __syncthreads();
    int warp = (blockIdx.x * blockDim.x + tid) >> 5;
    int lane = tid & 31;
    if (warp >= N_NODES) return;
    const float* hr = &g_h2[(size_t)warp * 128];
    const float* mr = &sme[lane * 129];
    float acc = 0.f;
    #pragma unroll
    for (int k4 = 0; k4 < 32; ++k4) {
        float4 v = *(const float4*)&hr[k4 * 4];
        acc += v.x * mr[k4 * 4 + 0];
        acc += v.y * mr[k4 * 4 + 1];
        acc += v.z * mr[k4 * 4 + 2];
        acc += v.w * mr[k4 * 4 + 3];
    }
    out[(size_t)warp * 32 + lane] = acc;
}

// ---------------- per-column stats + finalize ----------------
__global__ void k_colstats(const float* __restrict__ sc)
{
    __shared__ float red[256];
    int b = blockIdx.x, tid = threadIdx.x;
    float m = -INFINITY;
    for (int i = tid; i < N_NODES; i += 256)
        m = fmaxf(m, sc[(size_t)i * 32 + b]);
    red[tid] = m; __syncthreads();
    for (int off = 128; off > 0; off >>= 1) {
        if (tid < off) red[tid] = fmaxf(red[tid], red[tid + off]);
        __syncthreads();
    }
    float M = red[0];
    __syncthreads();
    float s = 0.f;
    for (int i = tid; i < N_NODES; i += 256)
        s += __expf(sc[(size_t)i * 32 + b] - M);
    red[tid] = s; __syncthreads();
    for (int off = 128; off > 0; off >>= 1) {
        if (tid < off) red[tid] += red[tid + off];
        __syncthreads();
    }
    if (tid == 0) {
        g_stats[b]      = M;
        g_stats[32 + b] = logf(red[0]);
    }
}

__global__ void k_finalize(float* __restrict__ out)
{
    int i = blockIdx.x * blockDim.x + threadIdx.x;
    if (i < N_NODES * 32) {
        int b = i & 31;
        out[i] = out[i] - g_stats[b] - g_stats[32 + b];
    }
}

// ---------------- launch ----------------
extern "C" void kernel_launch(void* const* d_in, const int* in_sizes, int n_in,
                              void* d_out, int out_size)
{
    const float* x       = (const float*)d_in[0];
    const void*  eidxraw = (const void*)d_in[1];
    const float* lh      = (const float*)d_in[2];
    const float* W1_rel  = (const float*)d_in[3];
    const float* W1_root = (const float*)d_in[4];
    const float* b1      = (const float*)d_in[5];
    const float* W2_rel  = (const float*)d_in[6];
    const float* W2_root = (const float*)d_in[7];
    const float* b2      = (const float*)d_in[8];
    const float* Wp      = (const float*)d_in[9];
    const float* bp      = (const float*)d_in[10];
    float*       out     = (float*)d_out;

    // opt into >48KB dynamic smem (attribute set; not a stream op — capture-safe)
    cudaFuncSetAttribute(k_layer_fused, cudaFuncAttributeMaxDynamicSharedMemorySize, SM_TOT);
    cudaGetLastError();

    const int GEMM_T = (N_NODES + 127) / 128;
    const int WARP_G = (N_NODES * 32 + 255) / 256;

    // CSR build
    k_detect_zero<<<SCAN_G, SCAN_B>>>((const unsigned int*)eidxraw);
    k_convert_count<<<(2 * N_EDGES + 255) / 256, 256>>>(eidxraw);
    k_blocksum<<<SCAN_G, SCAN_B>>>();
    k_scatter_rows<<<SCAN_G, SCAN_B>>>();
    k_fill<<<(N_EDGES + 255) / 256, 256>>>();

    // weight pre-split
    k_prep_w<<<(2 * 256 * 128 + 255) / 256, 256>>>(W1_rel, W1_root, W2_rel, W2_root);

    // fused layers
    k_layer_fused<<<GEMM_T, 256, SM_TOT>>>(x, b1, 0, 0, 0, N_NODES);
    k_layer_fused<<<GEMM_T, 256, SM_TOT>>>(x, b2, 1, 1, 1, N_NODES);

    // projection + scores + log_softmax(axis=0)
    k_proj<<<16, 256>>>(lh, Wp, bp);
    k_scores<<<WARP_G, 256>>>(out);
    k_colstats<<<32, 256>>>(out);
    k_finalize<<<(N_NODES * 32 + 255) / 256, 256>>>(out);
}

// round 16
// speedup vs baseline: 1.1556x; 1.1556x over previous
#include <cuda_runtime.h>
#include <cuda_bf16.h>
#include <math.h>
#include <stdint.h>

#define N_NODES 50000
#define N_EDGES 640000
#define FEAT    128
#define HIDDEN  512
#define BATCH   32

#define SCAN_B 256
#define SCAN_G ((N_NODES + SCAN_B - 1) / SCAN_B)   // 196

// ---------------- scratch (static device globals; no allocation) ----------------
__device__ float g_agg[(size_t)N_NODES * FEAT];
__device__ float g_h[(size_t)N_NODES * FEAT];
__device__ float g_h2[(size_t)N_NODES * FEAT];
__device__ int   g_eidx[2 * N_EDGES];
__device__ int   g_is64;
__device__ int   g_degi[N_NODES];
__device__ int   g_bsum[SCAN_G];
__device__ int   g_rowstart[N_NODES + 1];
__device__ int   g_cursor[N_NODES];
__device__ int   g_csr[N_EDGES];
__device__ float g_me[BATCH * FEAT];
__device__ float g_stats[64];
__device__ __nv_bfloat16 g_wsplit[2][2][256 * 128];

__device__ __forceinline__ uint32_t smem_u32(const void* p) {
    uint32_t a;
    asm("{ .reg .u64 t; cvta.to.shared.u64 t, %1; cvt.u32.u64 %0, t; }" : "=r"(a) : "l"(p));
    return a;
}
__device__ __forceinline__ void cp_async8(uint32_t saddr, const void* gaddr) {
    asm volatile("cp.async.ca.shared.global [%0], [%1], 8;" :: "r"(saddr), "l"(gaddr));
}
#define CP_COMMIT() asm volatile("cp.async.commit_group;" ::: "memory")
#define CP_WAIT0()  asm volatile("cp.async.wait_group 0;" ::: "memory")

// ---------------- detect dtype + zero degrees ----------------
__global__ void k_detect_zero(const unsigned int* __restrict__ raw) {
    int i = blockIdx.x * blockDim.x + threadIdx.x;
    if (i < N_NODES) g_degi[i] = 0;
    if (blockIdx.x == 0) {
        __shared__ int any_nz;
        if (threadIdx.x == 0) any_nz = 0;
        __syncthreads();
        int nz = 0;
        for (int p = threadIdx.x; p < 2048; p += 256)
            if (raw[2 * p + 1] != 0u) nz = 1;
        if (nz) atomicOr(&any_nz, 1);
        __syncthreads();
        if (threadIdx.x == 0) g_is64 = any_nz ? 0 : 1;
    }
}

__global__ void k_convert_count(const void* __restrict__ raw) {
    int e = blockIdx.x * blockDim.x + threadIdx.x;
    if (e >= 2 * N_EDGES) return;
    long long v;
    if (g_is64) v = ((const long long*)raw)[e];
    else        v = (long long)(((const int*)raw)[e]);
    int iv = (int)v;
    if (iv < 0) iv = 0;
    if (iv >= N_NODES) iv = N_NODES - 1;
    g_eidx[e] = iv;
    if (e >= N_EDGES) atomicAdd(&g_degi[iv], 1);
}

// ---------------- hierarchical scan ----------------
__global__ void k_blocksum() {
    __shared__ int red[SCAN_B];
    int i = blockIdx.x * SCAN_B + threadIdx.x;
    red[threadIdx.x] = (i < N_NODES) ? g_degi[i] : 0;
    __syncthreads();
    for (int off = SCAN_B / 2; off > 0; off >>= 1) {
        if (threadIdx.x < off) red[threadIdx.x] += red[threadIdx.x + off];
        __syncthreads();
    }
    if (threadIdx.x == 0) g_bsum[blockIdx.x] = red[0];
}

__global__ void k_scatter_rows() {
    __shared__ int wsum[8];
    __shared__ int boff;
    int tid = threadIdx.x;
    if (tid == 0) boff = 0;
    __syncthreads();
    if (tid < (int)blockIdx.x) atomicAdd(&boff, g_bsum[tid]);
    int i = blockIdx.x * SCAN_B + tid;
    int lane = tid & 31, wid = tid >> 5;
    int d = (i < N_NODES) ? g_degi[i] : 0;
    int v = d;
    #pragma unroll
    for (int off = 1; off < 32; off <<= 1) {
        int t = __shfl_up_sync(0xffffffffu, v, off);
        if (lane >= off) v += t;
    }
    if (lane == 31) wsum[wid] = v;
    __syncthreads();
    if (wid == 0 && lane < 8) {
        int w = wsum[lane];
        #pragma unroll
        for (int off = 1; off < 8; off <<= 1) {
            int t = __shfl_up_sync(0xffu, w, off);
            if (lane >= off) w += t;
        }
        wsum[lane] = w;
    }
    __syncthreads();
    int excl = v - d + (wid > 0 ? wsum[wid - 1] : 0) + boff;
    if (i < N_NODES) {
        g_rowstart[i] = excl;
        g_cursor[i]   = excl;
    }
    if (i == N_NODES - 1) g_rowstart[N_NODES] = excl + d;
}

__global__ void k_fill() {
    int e = blockIdx.x * blockDim.x + threadIdx.x;
    if (e < N_EDGES) {
        int d = g_eidx[N_EDGES + e];
        int pos = atomicAdd(&g_cursor[d], 1);
        if (pos >= 0 && pos < N_EDGES) g_csr[pos] = g_eidx[e];
    }
}

// ---------------- weight pre-split ----------------
__global__ void k_prep_w(const float* __restrict__ W1r, const float* __restrict__ W1o,
                         const float* __restrict__ W2r, const float* __restrict__ W2o)
{
    int idx = blockIdx.x * blockDim.x + threadIdx.x;
    if (idx >= 2 * 256 * 128) return;
    int l = idx >> 15;
    int e = idx & 32767;
    int k = e >> 7, n = e & 127;
    const float* W = (k < 128) ? (l ? W2r : W1r) : (l ? W2o : W1o);
    float v = W[(size_t)(k & 127) * 128 + n];
    __nv_bfloat16 h = __float2bfloat16(v);
    __nv_bfloat16 lo = __float2bfloat16(v - __bfloat162float(h));
    g_wsplit[l][0][e] = h;
    g_wsplit[l][1][e] = lo;
}

// ---------------- gather: g_agg[d] = mean over src of base[src] ----------------
__global__ void k_gather(const float* __restrict__ base, int from_h)
{
    const float* B = from_h ? (const float*)g_h : base;
    int warp = (blockIdx.x * blockDim.x + threadIdx.x) >> 5;
    int lane = threadIdx.x & 31;
    if (warp >= N_NODES) return;
    int beg = g_rowstart[warp];
    int end = g_rowstart[warp + 1];
    float4 acc = make_float4(0.f, 0.f, 0.f, 0.f);
    for (int j = beg; j < end; ++j) {
        int s = g_csr[j];
        float4 v = *(const float4*)&B[(size_t)s * 128 + lane * 4];
        acc.x += v.x; acc.y += v.y; acc.z += v.z; acc.w += v.w;
    }
    float invd = 1.0f / fmaxf((float)(end - beg), 1.0f);
    acc.x *= invd; acc.y *= invd; acc.z *= invd; acc.w *= invd;
    *(float4*)&g_agg[(size_t)warp * 128 + lane * 4] = acc;
}

// ---------------- mma.sync helpers ----------------
__device__ __forceinline__ void hmma16816(float* c, const uint32_t* a,
                                          uint32_t b0, uint32_t b1) {
    asm volatile(
        "mma.sync.aligned.m16n8k16.row.col.f32.bf16.bf16.f32 "
        "{%0,%1,%2,%3}, {%4,%5,%6,%7}, {%8,%9}, {%0,%1,%2,%3};"
        : "+f"(c[0]), "+f"(c[1]), "+f"(c[2]), "+f"(c[3])
        : "r"(a[0]), "r"(a[1]), "r"(a[2]), "r"(a[3]), "r"(b0), "r"(b1));
}
__device__ __forceinline__ void ldsm_x4(uint32_t* r, uint32_t addr) {
    asm volatile("ldmatrix.sync.aligned.m8n8.x4.shared.b16 {%0,%1,%2,%3}, [%4];"
                 : "=r"(r[0]), "=r"(r[1]), "=r"(r[2]), "=r"(r[3]) : "r"(addr));
}
__device__ __forceinline__ void ldsm_x4t(uint32_t* r, uint32_t addr) {
    asm volatile("ldmatrix.sync.aligned.m8n8.x4.trans.shared.b16 {%0,%1,%2,%3}, [%4];"
                 : "=r"(r[0]), "=r"(r[1]), "=r"(r[2]), "=r"(r[3]) : "r"(addr));
}
__device__ __forceinline__ void split_bf16(float v, __nv_bfloat16& h, __nv_bfloat16& l) {
    h = __float2bfloat16(v);
    l = __float2bfloat16(v - __bfloat162float(h));
}
__device__ __forceinline__ uint32_t pack2(__nv_bfloat16 a, __nv_bfloat16 b) {
    return (uint32_t)__bfloat16_as_ushort(a) | ((uint32_t)__bfloat16_as_ushort(b) << 16);
}

// ---------------- pipelined fused layer GEMM ----------------
// h_out = relu([agg | h_in] @ Wstack + b), K=256, N=128; bf16-split 3-product.
// Double-buffered SMEM, reg-prefetched A, cp.async B, ONE barrier per chunk.
#define SP_A 40
#define SP_B 136
#define A_IMG   (128 * SP_A * 2)          // 10240 B per plane
#define A_STAGE (2 * A_IMG)               // 20480 B per stage
#define B_IMG   (32 * SP_B * 2)           // 8704 B per plane
#define B_STAGE (2 * B_IMG)               // 17408 B per stage
#define SMO_B   (2 * A_STAGE)             // 40960
#define SM_TOT  (2 * A_STAGE + 2 * B_STAGE)   // 75776

__global__ __launch_bounds__(256, 2) void k_layer_gemm(
    const float* __restrict__ Hext,
    const float* __restrict__ bias,
    int layer, int h_sel, int c_sel, int M)
{
    extern __shared__ char smem[];
    const float* Hin = h_sel ? (const float*)g_h : Hext;
    float*       C   = c_sel ? g_h2 : g_h;
    int tid = threadIdx.x;
    int wid = tid >> 5, lane = tid & 31;
    int row0 = blockIdx.x * 128;
    int warp_m = wid >> 1, warp_n = wid & 1;
    int wrow = warp_m * 32;
    int wcol = warp_n * 64;

    uint32_t sbase = smem_u32(smem);
    int a_lr    = lane & 7;
    int a_half  = (lane >> 3) & 1;
    int a_khalf = lane >> 4;
    uint32_t a_off0 = (uint32_t)(wrow + a_lr + a_half * 8) * (SP_A * 2) + (uint32_t)a_khalf * 16;
    int b_lr   = lane & 15;
    int b_csel = lane >> 4;

    const __nv_bfloat16* Whi = g_wsplit[layer][0];
    const __nv_bfloat16* Wlo = g_wsplit[layer][1];

    // per-thread staging coords
    const int st_m  = tid >> 3;             // A: row (uses tid*8.. pattern over 4 iters)
    const int st_k4 = (tid & 7) * 4;
    const int sb_kk = tid >> 5;             // B: k row per iter
    const int sb_n4 = (tid & 31) * 4;

    float acc[2][8][4];
    #pragma unroll
    for (int mb = 0; mb < 2; ++mb)
        #pragma unroll
        for (int nb = 0; nb < 8; ++nb)
            #pragma unroll
            for (int q = 0; q < 4; ++q) acc[mb][nb][q] = 0.f;

    // A prefetch registers: 4 float4 per chunk
    float4 pre[2][4];

    // prologue: load chunk 0 A (from g_agg)
    #pragma unroll
    for (int it = 0; it < 4; ++it) {
        int m  = (tid + it * 256) >> 3;
        int gr = row0 + m;
        pre[0][it] = make_float4(0.f, 0.f, 0.f, 0.f);
        if (gr < M) pre[0][it] = *(const float4*)&g_agg[(size_t)gr * 128 + st_k4];
    }

    #pragma unroll
    for (int c = 0; c < 8; ++c) {
        const int stage = c & 1;
        const int nxt   = stage ^ 1;
        uint32_t aS = sbase + stage * A_STAGE;
        uint32_t bS = sbase + SMO_B + stage * B_STAGE;

        // stage A from regs (split + STS)
        #pragma unroll
        for (int it = 0; it < 4; ++it) {
            int m = (tid + it * 256) >> 3;
            float4 v = pre[stage][it];
            __nv_bfloat16 h0, l0, h1, l1, h2, l2, h3, l3;
            split_bf16(v.x, h0, l0); split_bf16(v.y, h1, l1);
            split_bf16(v.z, h2, l2); split_bf16(v.w, h3, l3);
            uint32_t doff = (uint32_t)m * (SP_A * 2) + (uint32_t)st_k4 * 2;
            *(uint2*)(smem + stage * A_STAGE + doff)         = make_uint2(pack2(h0, h1), pack2(h2, h3));
            *(uint2*)(smem + stage * A_STAGE + A_IMG + doff) = make_uint2(pack2(l0, l1), pack2(l2, l3));
        }
        // stage B via cp.async (pure copy of pre-split planes)
        {
            int k0 = c * 32;
            #pragma unroll
            for (int it = 0; it < 4; ++it) {
                int kk = sb_kk + it * 8;
                uint32_t soff = (uint32_t)(k0 + kk) * 128 + (uint32_t)sb_n4;
                uint32_t doff = (uint32_t)kk * (SP_B * 2) + (uint32_t)sb_n4 * 2;
                cp_async8(bS + doff,         &Whi[soff]);
                cp_async8(bS + B_IMG + doff, &Wlo[soff]);
            }
            CP_COMMIT();
        }
        // prefetch next A chunk into the other reg set (overlaps with MMA below)
        if (c < 7) {
            int nc = c + 1;
            const float* Asrc = (nc < 4) ? (const float*)g_agg : Hin;
            int ka = (nc * 32) & 127;
            #pragma unroll
            for (int it = 0; it < 4; ++it) {
                int m  = (tid + it * 256) >> 3;
                int gr = row0 + m;
                pre[nxt][it] = make_float4(0.f, 0.f, 0.f, 0.f);
                if (gr < M) pre[nxt][it] = *(const float4*)&Asrc[(size_t)gr * 128 + ka + st_k4];
            }
        }
        CP_WAIT0();
        __syncthreads();

        // MMA on this stage
        #pragma unroll
        for (int kk = 0; kk < 2; ++kk) {
            uint32_t ah[2][4], al[2][4];
            #pragma unroll
            for (int mb = 0; mb < 2; ++mb) {
                uint32_t ao = a_off0 + (uint32_t)(mb * 16) * (SP_A * 2) + (uint32_t)kk * 32;
                ldsm_x4(ah[mb], aS + ao);
                ldsm_x4(al[mb], aS + A_IMG + ao);
            }
            uint32_t b_row = (uint32_t)(kk * 16 + b_lr) * (SP_B * 2);
            #pragma unroll
            for (int nb2 = 0; nb2 < 4; ++nb2) {
                uint32_t bh[4], bl[4];
                uint32_t bcol = (uint32_t)(wcol + nb2 * 16 + b_csel * 8) * 2;
                ldsm_x4t(bh, bS + b_row + bcol);
                ldsm_x4t(bl, bS + B_IMG + b_row + bcol);
                #pragma unroll
                for (int hh = 0; hh < 2; ++hh) {
                    int nb = nb2 * 2 + hh;
                    #pragma unroll
                    for (int mb = 0; mb < 2; ++mb) {
                        hmma16816(acc[mb][nb], ah[mb], bh[2 * hh], bh[2 * hh + 1]);
                        hmma16816(acc[mb][nb], ah[mb], bl[2 * hh], bl[2 * hh + 1]);
                        hmma16816(acc[mb][nb], al[mb], bh[2 * hh], bh[2 * hh + 1]);
                    }
                }
            }
        }
        // NOTE: no end barrier needed — next staging writes the other stage,
        // which was last read two chunks ago and is fenced by the barrier above.
    }

    int g   = lane >> 2;
    int tig = lane & 3;
    #pragma unroll
    for (int nb = 0; nb < 8; ++nb) {
        int col = wcol + nb * 8 + tig * 2;
        float bb0 = bias[col], bb1 = bias[col + 1];
        #pragma unroll
        for (int mb = 0; mb < 2; ++mb) {
            int r0g = row0 + wrow + mb * 16 + g;
            int r1g = r0g + 8;
            float* a = acc[mb][nb];
            if (r0g < M)
                *(float2*)&C[(size_t)r0g * 128 + col] =
                    make_float2(fmaxf(a[0] + bb0, 0.f), fmaxf(a[1] + bb1, 0.f));
            if (r1g < M)
                *(float2*)&C[(size_t)r1g * 128 + col] =
                    make_float2(fmaxf(a[2] + bb0, 0.f), fmaxf(a[3] + bb1, 0.f));
        }
    }
}

// ---------------- projection ----------------
__global__ void k_proj(const float* __restrict__ lh, const float* __restrict__ Wp,
                       const float* __restrict__ bp)
{
    int idx = blockIdx.x * blockDim.x + threadIdx.x;
    if (idx >= BATCH * 128) return;
    int b = idx >> 7, j = idx & 127;
    float acc = bp[j];
    const float* lr = &lh[(size_t)b * HIDDEN];
    #pragma unroll 8
    for (int k = 0; k < HIDDEN; ++k)
        acc += lr[k] * Wp[(size_t)k * 128 + j];
    g_me[b * 128 + j] = acc;
}

// ---------------- scores ----------------
__global__ void k_scores(float* __restrict__ out)
{
    __shared__ float sme[32 * 129];
    int tid = threadIdx.x;
    for (int idx = tid; idx < 32 * 128; idx += blockDim.x) {
        int b = idx >> 7, k = idx & 127;
        sme[b * 129 + k] = g_me[idx];
    }
    __syncthreads();
    int warp = (blockIdx.x * blockDim.x + tid) >> 5;
    int lane = tid & 31;
    if (warp >= N_NODES) return;
    const float* hr = &g_h2[(size_t)warp * 128];
    const float* mr = &sme[lane * 129];
    float acc = 0.f;
    #pragma unroll
    for (int k4 = 0; k4 < 32; ++k4) {
        float4 v = *(const float4*)&hr[k4 * 4];
        acc += v.x * mr[k4 * 4 + 0];
        acc += v.y * mr[k4 * 4 + 1];
        acc += v.z * mr[k4 * 4 + 2];
        acc += v.w * mr[k4 * 4 + 3];
    }
    out[(size_t)warp * 32 + lane] = acc;
}

// ---------------- per-column stats + finalize ----------------
__global__ void k_colstats(const float* __restrict__ sc)
{
    __shared__ float red[256];
    int b = blockIdx.x, tid = threadIdx.x;
    float m = -INFINITY;
    for (int i = tid; i < N_NODES; i += 256)
        m = fmaxf(m, sc[(size_t)i * 32 + b]);
    red[tid] = m; __syncthreads();
    for (int off = 128; off > 0; off >>= 1) {
        if (tid < off) red[tid] = fmaxf(red[tid], red[tid + off]);
        __syncthreads();
    }
    float M = red[0];
    __syncthreads();
    float s = 0.f;
    for (int i = tid; i < N_NODES; i += 256)
        s += __expf(sc[(size_t)i * 32 + b] - M);
    red[tid] = s; __syncthreads();
    for (int off = 128; off > 0; off >>= 1) {
        if (tid < off) red[tid] += red[tid + off];
        __syncthreads();
    }
    if (tid == 0) {
        g_stats[b]      = M;
        g_stats[32 + b] = logf(red[0]);
    }
}

__global__ void k_finalize(float* __restrict__ out)
{
    int i = blockIdx.x * blockDim.x + threadIdx.x;
    if (i < N_NODES * 32) {
        int b = i & 31;
        out[i] = out[i] - g_stats[b] - g_stats[32 + b];
    }
}

// ---------------- launch ----------------
extern "C" void kernel_launch(void* const* d_in, const int* in_sizes, int n_in,
                              void* d_out, int out_size)
{
    const float* x       = (const float*)d_in[0];
    const void*  eidxraw = (const void*)d_in[1];
    const float* lh      = (const float*)d_in[2];
    const float* W1_rel  = (const float*)d_in[3];
    const float* W1_root = (const float*)d_in[4];
    const float* b1      = (const float*)d_in[5];
    const float* W2_rel  = (const float*)d_in[6];
    const float* W2_root = (const float*)d_in[7];
    const float* b2      = (const float*)d_in[8];
    const float* Wp      = (const float*)d_in[9];
    const float* bp      = (const float*)d_in[10];
    float*       out     = (float*)d_out;

    cudaFuncSetAttribute(k_layer_gemm, cudaFuncAttributeMaxDynamicSharedMemorySize, SM_TOT);
    cudaGetLastError();

    const int GEMM_T = (N_NODES + 127) / 128;
    const int WARP_G = (N_NODES * 32 + 255) / 256;

    // CSR build
    k_detect_zero<<<SCAN_G, SCAN_B>>>((const unsigned int*)eidxraw);
    k_convert_count<<<(2 * N_EDGES + 255) / 256, 256>>>(eidxraw);
    k_blocksum<<<SCAN_G, SCAN_B>>>();
    k_scatter_rows<<<SCAN_G, SCAN_B>>>();
    k_fill<<<(N_EDGES + 255) / 256, 256>>>();

    // weight pre-split
    k_prep_w<<<(2 * 256 * 128 + 255) / 256, 256>>>(W1_rel, W1_root, W2_rel, W2_root);

    // layer 1
    k_gather<<<WARP_G, 256>>>(x, 0);
    k_layer_gemm<<<GEMM_T, 256, SM_TOT>>>(x, b1, 0, 0, 0, N_NODES);
    // layer 2
    k_gather<<<WARP_G, 256>>>(x, 1);
    k_layer_gemm<<<GEMM_T, 256, SM_TOT>>>(x, b2, 1, 1, 1, N_NODES);

    // projection + scores + log_softmax(axis=0)
    k_proj<<<16, 256>>>(lh, Wp, bp);
    k_scores<<<WARP_G, 256>>>(out);
    k_colstats<<<32, 256>>>(out);
    k_finalize<<<(N_NODES * 32 + 255) / 256, 256>>>(out);
}

// round 17
// speedup vs baseline: 1.2086x; 1.0459x over previous
#include <cuda_runtime.h>
#include <cuda_bf16.h>
#include <math.h>
#include <stdint.h>

#define N_NODES 50000
#define N_EDGES 640000
#define FEAT    128
#define HIDDEN  512
#define BATCH   32

#define SCAN_B 256
#define SCAN_G ((N_NODES + SCAN_B - 1) / SCAN_B)   // 196
#define SCORE_G (N_NODES / 8)                       // 6250 blocks, 8 rows each
#define SUM_G  ((N_NODES + 255) / 256)              // 196

// ---------------- scratch (static device globals; no allocation) ----------------
__device__ float g_agg[(size_t)N_NODES * FEAT];
__device__ float g_h[(size_t)N_NODES * FEAT];
__device__ float g_h2[(size_t)N_NODES * FEAT];
__device__ int   g_eidx[2 * N_EDGES];
__device__ int   g_is64;
__device__ int   g_degi[N_NODES];
__device__ int   g_bsum[SCAN_G];
__device__ int   g_rowstart[N_NODES + 1];
__device__ int   g_cursor[N_NODES];
__device__ int   g_csr[N_EDGES];
__device__ float g_me[BATCH * FEAT];
__device__ float g_stats[64];                       // [b]=colmax, [32+b]=log(sumexp)
__device__ float g_pmax[SCORE_G * 32];
__device__ float g_psum[SUM_G * 32];
__device__ __nv_bfloat16 g_wsplit[2][2][256 * 128];

__device__ __forceinline__ uint32_t smem_u32(const void* p) {
    uint32_t a;
    asm("{ .reg .u64 t; cvta.to.shared.u64 t, %1; cvt.u32.u64 %0, t; }" : "=r"(a) : "l"(p));
    return a;
}
__device__ __forceinline__ void cp_async8(uint32_t saddr, const void* gaddr) {
    asm volatile("cp.async.ca.shared.global [%0], [%1], 8;" :: "r"(saddr), "l"(gaddr));
}
#define CP_COMMIT() asm volatile("cp.async.commit_group;" ::: "memory")
#define CP_WAIT0()  asm volatile("cp.async.wait_group 0;" ::: "memory")

// ---------------- detect dtype + zero degrees ----------------
__global__ void k_detect_zero(const unsigned int* __restrict__ raw) {
    int i = blockIdx.x * blockDim.x + threadIdx.x;
    if (i < N_NODES) g_degi[i] = 0;
    if (blockIdx.x == 0) {
        __shared__ int any_nz;
        if (threadIdx.x == 0) any_nz = 0;
        __syncthreads();
        int nz = 0;
        for (int p = threadIdx.x; p < 2048; p += 256)
            if (raw[2 * p + 1] != 0u) nz = 1;
        if (nz) atomicOr(&any_nz, 1);
        __syncthreads();
        if (threadIdx.x == 0) g_is64 = any_nz ? 0 : 1;
    }
}

__global__ void k_convert_count(const void* __restrict__ raw) {
    int e = blockIdx.x * blockDim.x + threadIdx.x;
    if (e >= 2 * N_EDGES) return;
    long long v;
    if (g_is64) v = ((const long long*)raw)[e];
    else        v = (long long)(((const int*)raw)[e]);
    int iv = (int)v;
    if (iv < 0) iv = 0;
    if (iv >= N_NODES) iv = N_NODES - 1;
    g_eidx[e] = iv;
    if (e >= N_EDGES) atomicAdd(&g_degi[iv], 1);
}

// ---------------- hierarchical scan ----------------
__global__ void k_blocksum() {
    __shared__ int red[SCAN_B];
    int i = blockIdx.x * SCAN_B + threadIdx.x;
    red[threadIdx.x] = (i < N_NODES) ? g_degi[i] : 0;
    __syncthreads();
    for (int off = SCAN_B / 2; off > 0; off >>= 1) {
        if (threadIdx.x < off) red[threadIdx.x] += red[threadIdx.x + off];
        __syncthreads();
    }
    if (threadIdx.x == 0) g_bsum[blockIdx.x] = red[0];
}

__global__ void k_scatter_rows() {
    __shared__ int wsum[8];
    __shared__ int boff;
    int tid = threadIdx.x;
    if (tid == 0) boff = 0;
    __syncthreads();
    if (tid < (int)blockIdx.x) atomicAdd(&boff, g_bsum[tid]);
    int i = blockIdx.x * SCAN_B + tid;
    int lane = tid & 31, wid = tid >> 5;
    int d = (i < N_NODES) ? g_degi[i] : 0;
    int v = d;
    #pragma unroll
    for (int off = 1; off < 32; off <<= 1) {
        int t = __shfl_up_sync(0xffffffffu, v, off);
        if (lane >= off) v += t;
    }
    if (lane == 31) wsum[wid] = v;
    __syncthreads();
    if (wid == 0 && lane < 8) {
        int w = wsum[lane];
        #pragma unroll
        for (int off = 1; off < 8; off <<= 1) {
            int t = __shfl_up_sync(0xffu, w, off);
            if (lane >= off) w += t;
        }
        wsum[lane] = w;
    }
    __syncthreads();
    int excl = v - d + (wid > 0 ? wsum[wid - 1] : 0) + boff;
    if (i < N_NODES) {
        g_rowstart[i] = excl;
        g_cursor[i]   = excl;
    }
    if (i == N_NODES - 1) g_rowstart[N_NODES] = excl + d;
}

__global__ void k_fill() {
    int e = blockIdx.x * blockDim.x + threadIdx.x;
    if (e < N_EDGES) {
        int d = g_eidx[N_EDGES + e];
        int pos = atomicAdd(&g_cursor[d], 1);
        if (pos >= 0 && pos < N_EDGES) g_csr[pos] = g_eidx[e];
    }
}

// ---------------- weight pre-split ----------------
__global__ void k_prep_w(const float* __restrict__ W1r, const float* __restrict__ W1o,
                         const float* __restrict__ W2r, const float* __restrict__ W2o)
{
    int idx = blockIdx.x * blockDim.x + threadIdx.x;
    if (idx >= 2 * 256 * 128) return;
    int l = idx >> 15;
    int e = idx & 32767;
    int k = e >> 7, n = e & 127;
    const float* W = (k < 128) ? (l ? W2r : W1r) : (l ? W2o : W1o);
    float v = W[(size_t)(k & 127) * 128 + n];
    __nv_bfloat16 h = __float2bfloat16(v);
    __nv_bfloat16 lo = __float2bfloat16(v - __bfloat162float(h));
    g_wsplit[l][0][e] = h;
    g_wsplit[l][1][e] = lo;
}

// ---------------- gather: g_agg[d] = mean over src of base[src] ----------------
__global__ void k_gather(const float* __restrict__ base, int from_h)
{
    const float* B = from_h ? (const float*)g_h : base;
    int warp = (blockIdx.x * blockDim.x + threadIdx.x) >> 5;
    int lane = threadIdx.x & 31;
    if (warp >= N_NODES) return;
    int beg = g_rowstart[warp];
    int end = g_rowstart[warp + 1];
    float4 acc = make_float4(0.f, 0.f, 0.f, 0.f);
    for (int j = beg; j < end; ++j) {
        int s = g_csr[j];
        float4 v = *(const float4*)&B[(size_t)s * 128 + lane * 4];
        acc.x += v.x; acc.y += v.y; acc.z += v.z; acc.w += v.w;
    }
    float invd = 1.0f / fmaxf((float)(end - beg), 1.0f);
    acc.x *= invd; acc.y *= invd; acc.z *= invd; acc.w *= invd;
    *(float4*)&g_agg[(size_t)warp * 128 + lane * 4] = acc;
}

// ---------------- mma.sync helpers ----------------
__device__ __forceinline__ void hmma16816(float* c, const uint32_t* a,
                                          uint32_t b0, uint32_t b1) {
    asm volatile(
        "mma.sync.aligned.m16n8k16.row.col.f32.bf16.bf16.f32 "
        "{%0,%1,%2,%3}, {%4,%5,%6,%7}, {%8,%9}, {%0,%1,%2,%3};"
        : "+f"(c[0]), "+f"(c[1]), "+f"(c[2]), "+f"(c[3])
        : "r"(a[0]), "r"(a[1]), "r"(a[2]), "r"(a[3]), "r"(b0), "r"(b1));
}
__device__ __forceinline__ void ldsm_x4(uint32_t* r, uint32_t addr) {
    asm volatile("ldmatrix.sync.aligned.m8n8.x4.shared.b16 {%0,%1,%2,%3}, [%4];"
                 : "=r"(r[0]), "=r"(r[1]), "=r"(r[2]), "=r"(r[3]) : "r"(addr));
}
__device__ __forceinline__ void ldsm_x4t(uint32_t* r, uint32_t addr) {
    asm volatile("ldmatrix.sync.aligned.m8n8.x4.trans.shared.b16 {%0,%1,%2,%3}, [%4];"
                 : "=r"(r[0]), "=r"(r[1]), "=r"(r[2]), "=r"(r[3]) : "r"(addr));
}
__device__ __forceinline__ void split_bf16(float v, __nv_bfloat16& h, __nv_bfloat16& l) {
    h = __float2bfloat16(v);
    l = __float2bfloat16(v - __bfloat162float(h));
}
__device__ __forceinline__ uint32_t pack2(__nv_bfloat16 a, __nv_bfloat16 b) {
    return (uint32_t)__bfloat16_as_ushort(a) | ((uint32_t)__bfloat16_as_ushort(b) << 16);
}

// ---------------- pipelined fused layer GEMM ----------------
#define SP_A 40
#define SP_B 136
#define A_IMG   (128 * SP_A * 2)
#define A_STAGE (2 * A_IMG)
#define B_IMG   (32 * SP_B * 2)
#define B_STAGE (2 * B_IMG)
#define SMO_B   (2 * A_STAGE)
#define SM_TOT  (2 * A_STAGE + 2 * B_STAGE)

__global__ __launch_bounds__(256, 2) void k_layer_gemm(
    const float* __restrict__ Hext,
    const float* __restrict__ bias,
    int layer, int h_sel, int c_sel, int M)
{
    extern __shared__ char smem[];
    const float* Hin = h_sel ? (const float*)g_h : Hext;
    float*       C   = c_sel ? g_h2 : g_h;
    int tid = threadIdx.x;
    int wid = tid >> 5, lane = tid & 31;
    int row0 = blockIdx.x * 128;
    int warp_m = wid >> 1, warp_n = wid & 1;
    int wrow = warp_m * 32;
    int wcol = warp_n * 64;

    uint32_t sbase = smem_u32(smem);
    int a_lr    = lane & 7;
    int a_half  = (lane >> 3) & 1;
    int a_khalf = lane >> 4;
    uint32_t a_off0 = (uint32_t)(wrow + a_lr + a_half * 8) * (SP_A * 2) + (uint32_t)a_khalf * 16;
    int b_lr   = lane & 15;
    int b_csel = lane >> 4;

    const __nv_bfloat16* Whi = g_wsplit[layer][0];
    const __nv_bfloat16* Wlo = g_wsplit[layer][1];

    const int st_k4 = (tid & 7) * 4;
    const int sb_kk = tid >> 5;
    const int sb_n4 = (tid & 31) * 4;

    float acc[2][8][4];
    #pragma unroll
    for (int mb = 0; mb < 2; ++mb)
        #pragma unroll
        for (int nb = 0; nb < 8; ++nb)
            #pragma unroll
            for (int q = 0; q < 4; ++q) acc[mb][nb][q] = 0.f;

    float4 pre[2][4];
    #pragma unroll
    for (int it = 0; it < 4; ++it) {
        int m  = (tid + it * 256) >> 3;
        int gr = row0 + m;
        pre[0][it] = make_float4(0.f, 0.f, 0.f, 0.f);
        if (gr < M) pre[0][it] = *(const float4*)&g_agg[(size_t)gr * 128 + st_k4];
    }

    #pragma unroll
    for (int c = 0; c < 8; ++c) {
        const int stage = c & 1;
        const int nxt   = stage ^ 1;
        uint32_t aS = sbase + stage * A_STAGE;
        uint32_t bS = sbase + SMO_B + stage * B_STAGE;

        #pragma unroll
        for (int it = 0; it < 4; ++it) {
            int m = (tid + it * 256) >> 3;
            float4 v = pre[stage][it];
            __nv_bfloat16 h0, l0, h1, l1, h2, l2, h3, l3;
            split_bf16(v.x, h0, l0); split_bf16(v.y, h1, l1);
            split_bf16(v.z, h2, l2); split_bf16(v.w, h3, l3);
            uint32_t doff = (uint32_t)m * (SP_A * 2) + (uint32_t)st_k4 * 2;
            *(uint2*)(smem + stage * A_STAGE + doff)         = make_uint2(pack2(h0, h1), pack2(h2, h3));
            *(uint2*)(smem + stage * A_STAGE + A_IMG + doff) = make_uint2(pack2(l0, l1), pack2(l2, l3));
        }
        {
            int k0 = c * 32;
            #pragma unroll
            for (int it = 0; it < 4; ++it) {
                int kk = sb_kk + it * 8;
                uint32_t soff = (uint32_t)(k0 + kk) * 128 + (uint32_t)sb_n4;
                uint32_t doff = (uint32_t)kk * (SP_B * 2) + (uint32_t)sb_n4 * 2;
                cp_async8(bS + doff,         &Whi[soff]);
                cp_async8(bS + B_IMG + doff, &Wlo[soff]);
            }
            CP_COMMIT();
        }
        if (c < 7) {
            int nc = c + 1;
            const float* Asrc = (nc < 4) ? (const float*)g_agg : Hin;
            int ka = (nc * 32) & 127;
            #pragma unroll
            for (int it = 0; it < 4; ++it) {
                int m  = (tid + it * 256) >> 3;
                int gr = row0 + m;
                pre[nxt][it] = make_float4(0.f, 0.f, 0.f, 0.f);
                if (gr < M) pre[nxt][it] = *(const float4*)&Asrc[(size_t)gr * 128 + ka + st_k4];
            }
        }
        CP_WAIT0();
        __syncthreads();

        #pragma unroll
        for (int kk = 0; kk < 2; ++kk) {
            uint32_t ah[2][4], al[2][4];
            #pragma unroll
            for (int mb = 0; mb < 2; ++mb) {
                uint32_t ao = a_off0 + (uint32_t)(mb * 16) * (SP_A * 2) + (uint32_t)kk * 32;
                ldsm_x4(ah[mb], aS + ao);
                ldsm_x4(al[mb], aS + A_IMG + ao);
            }
            uint32_t b_row = (uint32_t)(kk * 16 + b_lr) * (SP_B * 2);
            #pragma unroll
            for (int nb2 = 0; nb2 < 4; ++nb2) {
                uint32_t bh[4], bl[4];
                uint32_t bcol = (uint32_t)(wcol + nb2 * 16 + b_csel * 8) * 2;
                ldsm_x4t(bh, bS + b_row + bcol);
                ldsm_x4t(bl, bS + B_IMG + b_row + bcol);
                #pragma unroll
                for (int hh = 0; hh < 2; ++hh) {
                    int nb = nb2 * 2 + hh;
                    #pragma unroll
                    for (int mb = 0; mb < 2; ++mb) {
                        hmma16816(acc[mb][nb], ah[mb], bh[2 * hh], bh[2 * hh + 1]);
                        hmma16816(acc[mb][nb], ah[mb], bl[2 * hh], bl[2 * hh + 1]);
                        hmma16816(acc[mb][nb], al[mb], bh[2 * hh], bh[2 * hh + 1]);
                    }
                }
            }
        }
    }

    int g   = lane >> 2;
    int tig = lane & 3;
    #pragma unroll
    for (int nb = 0; nb < 8; ++nb) {
        int col = wcol + nb * 8 + tig * 2;
        float bb0 = bias[col], bb1 = bias[col + 1];
        #pragma unroll
        for (int mb = 0; mb < 2; ++mb) {
            int r0g = row0 + wrow + mb * 16 + g;
            int r1g = r0g + 8;
            float* a = acc[mb][nb];
            if (r0g < M)
                *(float2*)&C[(size_t)r0g * 128 + col] =
                    make_float2(fmaxf(a[0] + bb0, 0.f), fmaxf(a[1] + bb1, 0.f));
            if (r1g < M)
                *(float2*)&C[(size_t)r1g * 128 + col] =
                    make_float2(fmaxf(a[2] + bb0, 0.f), fmaxf(a[3] + bb1, 0.f));
        }
    }
}

// ---------------- projection ----------------
__global__ void k_proj(const float* __restrict__ lh, const float* __restrict__ Wp,
                       const float* __restrict__ bp)
{
    int idx = blockIdx.x * blockDim.x + threadIdx.x;
    if (idx >= BATCH * 128) return;
    int b = idx >> 7, j = idx & 127;
    float acc = bp[j];
    const float* lr = &lh[(size_t)b * HIDDEN];
    #pragma unroll 8
    for (int k = 0; k < HIDDEN; ++k)
        acc += lr[k] * Wp[(size_t)k * 128 + j];
    g_me[b * 128 + j] = acc;
}

// ---------------- scores + per-block column max ----------------
__global__ void k_scores(float* __restrict__ out)
{
    __shared__ float sme[32 * 129];
    __shared__ float smax[8][32];
    int tid = threadIdx.x;
    for (int idx = tid; idx < 32 * 128; idx += blockDim.x) {
        int b = idx >> 7, k = idx & 127;
        sme[b * 129 + k] = g_me[idx];
    }
    __syncthreads();
    int wid  = tid >> 5;
    int lane = tid & 31;
    int row  = blockIdx.x * 8 + wid;          // SCORE_G*8 == N_NODES exactly
    const float* hr = &g_h2[(size_t)row * 128];
    const float* mr = &sme[lane * 129];
    float acc = 0.f;
    #pragma unroll
    for (int k4 = 0; k4 < 32; ++k4) {
        float4 v = *(const float4*)&hr[k4 * 4];
        acc += v.x * mr[k4 * 4 + 0];
        acc += v.y * mr[k4 * 4 + 1];
        acc += v.z * mr[k4 * 4 + 2];
        acc += v.w * mr[k4 * 4 + 3];
    }
    out[(size_t)row * 32 + lane] = acc;
    smax[wid][lane] = acc;
    __syncthreads();
    if (wid == 0) {
        float m = smax[0][lane];
        #pragma unroll
        for (int w = 1; w < 8; ++w) m = fmaxf(m, smax[w][lane]);
        g_pmax[blockIdx.x * 32 + lane] = m;
    }
}

// ---------------- column max final: 32 blocks ----------------
__global__ void k_colmax_fin()
{
    __shared__ float red[256];
    int b = blockIdx.x, tid = threadIdx.x;
    float m = -INFINITY;
    for (int i = tid; i < SCORE_G; i += 256)
        m = fmaxf(m, g_pmax[i * 32 + b]);
    red[tid] = m; __syncthreads();
    for (int off = 128; off > 0; off >>= 1) {
        if (tid < off) red[tid] = fmaxf(red[tid], red[tid + off]);
        __syncthreads();
    }
    if (tid == 0) g_stats[b] = red[0];
}

// ---------------- column sumexp partials: slab-parallel, coalesced ----------------
__global__ void k_colsum(const float* __restrict__ sc)
{
    __shared__ float sred[256][32];
    __shared__ float cmax[32];
    int tid = threadIdx.x;
    if (tid < 32) cmax[tid] = g_stats[tid];
    __syncthreads();
    int r = blockIdx.x * 256 + tid;
    float s[32];
    #pragma unroll
    for (int c = 0; c < 32; ++c) s[c] = 0.f;
    if (r < N_NODES) {
        const float* row = &sc[(size_t)r * 32];
        #pragma unroll
        for (int c4 = 0; c4 < 8; ++c4) {
            float4 v = *(const float4*)&row[c4 * 4];
            s[c4 * 4 + 0] = __expf(v.x - cmax[c4 * 4 + 0]);
            s[c4 * 4 + 1] = __expf(v.y - cmax[c4 * 4 + 1]);
            s[c4 * 4 + 2] = __expf(v.z - cmax[c4 * 4 + 2]);
            s[c4 * 4 + 3] = __expf(v.w - cmax[c4 * 4 + 3]);
        }
    }
    #pragma unroll
    for (int c = 0; c < 32; ++c) sred[tid][c] = s[c];
    __syncthreads();
    for (int off = 128; off > 0; off >>= 1) {
        if (tid < off) {
            #pragma unroll
            for (int c = 0; c < 32; ++c) sred[tid][c] += sred[tid + off][c];
        }
        __syncthreads();
    }
    if (tid < 32) g_psum[blockIdx.x * 32 + tid] = sred[0][tid];
}

// ---------------- column sumexp final: 1 block ----------------
__global__ void k_colsum_fin()
{
    int c = threadIdx.x;
    if (c < 32) {
        float s = 0.f;
        for (int i = 0; i < SUM_G; ++i) s += g_psum[i * 32 + c];
        g_stats[32 + c] = logf(s);
    }
}

__global__ void k_finalize(float* __restrict__ out)
{
    int i = blockIdx.x * blockDim.x + threadIdx.x;
    if (i < N_NODES * 32) {
        int b = i & 31;
        out[i] = out[i] - g_stats[b] - g_stats[32 + b];
    }
}

// ---------------- launch ----------------
extern "C" void kernel_launch(void* const* d_in, const int* in_sizes, int n_in,
                              void* d_out, int out_size)
{
    const float* x       = (const float*)d_in[0];
    const void*  eidxraw = (const void*)d_in[1];
    const float* lh      = (const float*)d_in[2];
    const float* W1_rel  = (const float*)d_in[3];
    const float* W1_root = (const float*)d_in[4];
    const float* b1      = (const float*)d_in[5];
    const float* W2_rel  = (const float*)d_in[6];
    const float* W2_root = (const float*)d_in[7];
    const float* b2      = (const float*)d_in[8];
    const float* Wp      = (const float*)d_in[9];
    const float* bp      = (const float*)d_in[10];
    float*       out     = (float*)d_out;

    cudaFuncSetAttribute(k_layer_gemm, cudaFuncAttributeMaxDynamicSharedMemorySize, SM_TOT);
    cudaGetLastError();

    const int GEMM_T = (N_NODES + 127) / 128;
    const int WARP_G = (N_NODES * 32 + 255) / 256;

    // CSR build
    k_detect_zero<<<SCAN_G, SCAN_B>>>((const unsigned int*)eidxraw);
    k_convert_count<<<(2 * N_EDGES + 255) / 256, 256>>>(eidxraw);
    k_blocksum<<<SCAN_G, SCAN_B>>>();
    k_scatter_rows<<<SCAN_G, SCAN_B>>>();
    k_fill<<<(N_EDGES + 255) / 256, 256>>>();

    // weight pre-split
    k_prep_w<<<(2 * 256 * 128 + 255) / 256, 256>>>(W1_rel, W1_root, W2_rel, W2_root);

    // layer 1
    k_gather<<<WARP_G, 256>>>(x, 0);
    k_layer_gemm<<<GEMM_T, 256, SM_TOT>>>(x, b1, 0, 0, 0, N_NODES);
    // layer 2
    k_gather<<<WARP_G, 256>>>(x, 1);
    k_layer_gemm<<<GEMM_T, 256, SM_TOT>>>(x, b2, 1, 1, 1, N_NODES);

    // projection + scores + log_softmax(axis=0)
    k_proj<<<16, 256>>>(lh, Wp, bp);
    k_scores<<<SCORE_G, 256>>>(out);
    k_colmax_fin<<<32, 256>>>();
    k_colsum<<<SUM_G, 256>>>(out);
    k_colsum_fin<<<1, 32>>>();
    k_finalize<<<(N_NODES * 32 + 255) / 256, 256>>>(out);
}